// round 16
// baseline (speedup 1.0000x reference)
#include <cuda_runtime.h>
#include <cuda_bf16.h>
#include <cuda_fp16.h>
#include <math.h>
#include <stdint.h>

#define B_ 4
#define T_ 512
#define D_ 768
#define H_ 12
#define HD_ 64
#define L_ 12
#define DFF_ 2048
#define VOCAB_ 50257
#define NMEM_ 1024
#define TOPK_ 8
#define NLAT_ 4
#define CAP_ 64
#define BT_ (B_*T_)
#define QKVD_ (3*D_)
#define BC_ (B_*CAP_)   // 256 compacted rows

// ------------------- scratch (device globals; no allocation) -------------------
__device__ float g_X[BT_*D_];
__device__ float g_Y[BT_*D_];
__device__ float g_Hb[BT_*D_];
__device__ float g_QKV[BT_*QKVD_];
__device__ float g_ATT[BT_*D_];
__device__ float g_U[BT_*DFF_];
__device__ float g_V2[BT_*DFF_];
__device__ float g_SIM[BT_*NMEM_];
__device__ float g_RETP[BT_*D_];
__device__ float g_RET[BT_*D_];
__device__ float g_GI[BT_*2*D_];
__device__ float g_H1[BT_*(D_/2)];
__device__ float g_SC[BT_];
__device__ int   g_CIDX[BT_];

__device__ __forceinline__ void cp_async16(void* smem, const void* gmem) {
    uint32_t s = (uint32_t)__cvta_generic_to_shared(smem);
    asm volatile("cp.async.cg.shared.global [%0], [%1], 16;" :: "r"(s), "l"(gmem));
}

// ==================== 3x-split FP16 mma.sync GEMM (m16n8k16) ====================
#define PITCH2 12
#define TILE_U (128 * PITCH2)

__device__ __forceinline__ uint32_t pkh(__half a, __half b) {
    __half2 h = __halves2half2(a, b);
    return *(uint32_t*)&h;
}

__device__ __forceinline__ void mma_f16(float* c, uint32_t a0, uint32_t a1,
                                        uint32_t a2, uint32_t a3,
                                        uint32_t b0, uint32_t b1) {
    asm volatile(
        "mma.sync.aligned.m16n8k16.row.col.f32.f16.f16.f32 "
        "{%0,%1,%2,%3}, {%4,%5,%6,%7}, {%8,%9}, {%0,%1,%2,%3};"
        : "+f"(c[0]), "+f"(c[1]), "+f"(c[2]), "+f"(c[3])
        : "r"(a0), "r"(a1), "r"(a2), "r"(a3), "r"(b0), "r"(b1));
}

__device__ __forceinline__ float4 silu_mul4(float4 u, float4 v) {
    return make_float4(u.x / (1.f + expf(-u.x)) * v.x,
                       u.y / (1.f + expf(-u.y)) * v.y,
                       u.z / (1.f + expf(-u.z)) * v.z,
                       u.w / (1.f + expf(-u.w)) * v.w);
}

// SWIGLU: A-operand = silu(A)*A2 elementwise. TERMS: 3 = full split, 2 = drop ah*bl.
template<bool ACC, bool NGUARD, bool SWIGLU, int TERMS>
__global__ __launch_bounds__(256, 2) void mmah_gemm_nt(const float* __restrict__ A,
                                                       const float* __restrict__ A2,
                                                       const float* __restrict__ Bw,
                                                       float* __restrict__ C,
                                                       int M, int N, int K) {
    __shared__ uint32_t smu[2 * 4 * TILE_U];
    const int bm = blockIdx.y * 128, bn = blockIdx.x * 128;
    const int tid = threadIdx.x;
    const int wid = tid >> 5, lane = tid & 31;
    const int warp_m = wid >> 2, warp_n = wid & 3;
    const int g = lane >> 2, tg = lane & 3;

    float acc[4][4][4];
#pragma unroll
    for (int mi = 0; mi < 4; mi++)
#pragma unroll
        for (int ni = 0; ni < 4; ni++)
#pragma unroll
            for (int e = 0; e < 4; e++) acc[mi][ni][e] = 0.f;

    const int r_0 = tid >> 2,         c4_0 = (tid & 3);
    const int r_1 = (tid + 256) >> 2, c4_1 = ((tid + 256) & 3);
    const float* a0p = A + (size_t)(bm + r_0) * K + c4_0 * 4;
    const float* a1p = A + (size_t)(bm + r_1) * K + c4_1 * 4;
    const float* a0q = SWIGLU ? A2 + (size_t)(bm + r_0) * K + c4_0 * 4 : nullptr;
    const float* a1q = SWIGLU ? A2 + (size_t)(bm + r_1) * K + c4_1 * 4 : nullptr;
    const bool b0ok = !NGUARD || (bn + r_0) < N;
    const bool b1ok = !NGUARD || (bn + r_1) < N;
    const float* b0p = Bw + (size_t)(bn + r_0) * K + c4_0 * 4;
    const float* b1p = Bw + (size_t)(bn + r_1) * K + c4_1 * 4;

    const int nt = K >> 4;
    float4 ra0, ra1, rb0, rb1, rv0, rv1;

    ra0 = *(const float4*)(a0p);
    ra1 = *(const float4*)(a1p);
    if (SWIGLU) { rv0 = *(const float4*)(a0q); rv1 = *(const float4*)(a1q); }
    rb0 = b0ok ? *(const float4*)(b0p) : make_float4(0.f, 0.f, 0.f, 0.f);
    rb1 = b1ok ? *(const float4*)(b1p) : make_float4(0.f, 0.f, 0.f, 0.f);

    for (int t = 0; t < nt; t++) {
        const int s = t & 1;
        uint32_t* st = smu + s * 4 * TILE_U;
        {
            auto put = [&](uint32_t* tH, uint32_t* tL, int r, int c4, float4 v) {
                __half hx = __float2half_rn(v.x), hy = __float2half_rn(v.y);
                __half hz = __float2half_rn(v.z), hw = __float2half_rn(v.w);
                uint32_t h0 = pkh(hx, hy), h1 = pkh(hz, hw);
                uint32_t l0 = pkh(__float2half_rn(v.x - __half2float(hx)),
                                  __float2half_rn(v.y - __half2float(hy)));
                uint32_t l1 = pkh(__float2half_rn(v.z - __half2float(hz)),
                                  __float2half_rn(v.w - __half2float(hw)));
                int idx = r * PITCH2 + c4 * 2;
                *(uint2*)&tH[idx] = make_uint2(h0, h1);
                *(uint2*)&tL[idx] = make_uint2(l0, l1);
            };
            float4 va0 = SWIGLU ? silu_mul4(ra0, rv0) : ra0;
            float4 va1 = SWIGLU ? silu_mul4(ra1, rv1) : ra1;
            put(st,              st + TILE_U,     r_0, c4_0, va0);
            put(st,              st + TILE_U,     r_1, c4_1, va1);
            put(st + 2 * TILE_U, st + 3 * TILE_U, r_0, c4_0, rb0);
            put(st + 2 * TILE_U, st + 3 * TILE_U, r_1, c4_1, rb1);
        }
        if (t + 1 < nt) {
            const int k0 = (t + 1) << 4;
            ra0 = *(const float4*)(a0p + k0);
            ra1 = *(const float4*)(a1p + k0);
            if (SWIGLU) { rv0 = *(const float4*)(a0q + k0); rv1 = *(const float4*)(a1q + k0); }
            rb0 = b0ok ? *(const float4*)(b0p + k0) : make_float4(0.f, 0.f, 0.f, 0.f);
            rb1 = b1ok ? *(const float4*)(b1p + k0) : make_float4(0.f, 0.f, 0.f, 0.f);
        }
        __syncthreads();

        const uint32_t* Ah = smu + s * 4 * TILE_U;
        const uint32_t* Al = Ah + TILE_U;
        const uint32_t* Bh = Ah + 2 * TILE_U;
        const uint32_t* Bl = Ah + 3 * TILE_U;

        uint32_t bh[4][2], bl[4][2];
#pragma unroll
        for (int ni = 0; ni < 4; ni++) {
            const int rb = (warp_n * 32 + ni * 8 + g) * PITCH2 + tg;
            bh[ni][0] = Bh[rb]; bh[ni][1] = Bh[rb + 4];
            if (TERMS == 3) { bl[ni][0] = Bl[rb]; bl[ni][1] = Bl[rb + 4]; }
        }
#pragma unroll
        for (int mi = 0; mi < 4; mi++) {
            const int ra = (warp_m * 64 + mi * 16 + g) * PITCH2 + tg;
            const uint32_t ah0 = Ah[ra], ah1 = Ah[ra + 8 * PITCH2];
            const uint32_t ah2 = Ah[ra + 4], ah3 = Ah[ra + 8 * PITCH2 + 4];
            const uint32_t al0 = Al[ra], al1 = Al[ra + 8 * PITCH2];
            const uint32_t al2 = Al[ra + 4], al3 = Al[ra + 8 * PITCH2 + 4];
#pragma unroll
            for (int ni = 0; ni < 4; ni++) {
                mma_f16(acc[mi][ni], al0, al1, al2, al3, bh[ni][0], bh[ni][1]);
                if (TERMS == 3)
                    mma_f16(acc[mi][ni], ah0, ah1, ah2, ah3, bl[ni][0], bl[ni][1]);
                mma_f16(acc[mi][ni], ah0, ah1, ah2, ah3, bh[ni][0], bh[ni][1]);
            }
        }
    }

#pragma unroll
    for (int mi = 0; mi < 4; mi++) {
#pragma unroll
        for (int ni = 0; ni < 4; ni++) {
            int row0 = bm + warp_m * 64 + mi * 16 + g;
            int col = bn + warp_n * 32 + ni * 8 + tg * 2;
#pragma unroll
            for (int rr = 0; rr < 2; rr++) {
                int row = row0 + rr * 8;
                float* cp = C + (size_t)row * N + col;
                float v0 = acc[mi][ni][rr * 2 + 0];
                float v1 = acc[mi][ni][rr * 2 + 1];
                if (!NGUARD || col + 1 < N) {
                    if (ACC) { cp[0] += v0; cp[1] += v1; }
                    else     { cp[0] = v0;  cp[1] = v1; }
                } else if (col < N) {
                    if (ACC) cp[0] += v0; else cp[0] = v0;
                }
            }
        }
    }
}

// ==================== fused flash-style attention (cp.async K/V pipeline) ========
#define APITCH 68
#define TSZ (64 * APITCH)                 // floats per tile
#define FA_SMEM (6 * TSZ * 4)             // Q + 2x(K,V) + P
#define FAM_SMEM (FA_SMEM + 256)

// Full attention: grid (T/64, B*H); QKV [BT][2304]; O [BT][768]
__global__ __launch_bounds__(256) void fattn_k(const float* __restrict__ QKV,
                                               float* __restrict__ O) {
    extern __shared__ float sm[];
    float* Qs = sm;
    float* Ps = sm + 5 * TSZ;
    const int qt = gridDim.x - 1 - blockIdx.x;  // long blocks first
    const int bh = blockIdx.y;
    const int b = bh / H_, h = bh % H_;
    const int tid = threadIdx.x;
    const int q0 = qt * 64;
    for (int i = tid; i < 64 * 16; i += 256) {
        int r = i >> 4, c4 = i & 15;
        *(float4*)(Qs + r * APITCH + c4 * 4) =
            *(const float4*)(QKV + (size_t)(b * T_ + q0 + r) * QKVD_ + h * HD_ + c4 * 4);
    }
    const int q = tid >> 2, sub = tid & 3;
    const int qglob = q0 + q;
    int rr_[4], cc_[4];
#pragma unroll
    for (int j = 0; j < 4; j++) { int i = tid + 256 * j; rr_[j] = i >> 4; cc_[j] = i & 15; }

    auto issue_kv = [&](int kt, int buf) {
        float* Kd = sm + (1 + 2 * buf) * TSZ;
        float* Vd = sm + (2 + 2 * buf) * TSZ;
#pragma unroll
        for (int j = 0; j < 4; j++) {
            const float* src = QKV + (size_t)(b * T_ + kt * 64 + rr_[j]) * QKVD_
                               + h * HD_ + cc_[j] * 4;
            cp_async16(Kd + rr_[j] * APITCH + cc_[j] * 4, src + D_);
            cp_async16(Vd + rr_[j] * APITCH + cc_[j] * 4, src + 2 * D_);
        }
        asm volatile("cp.async.commit_group;");
    };

    float m_i = -1e30f, l_i = 0.f;
    float acc[16];
#pragma unroll
    for (int i = 0; i < 16; i++) acc[i] = 0.f;

    issue_kv(0, 0);
    for (int kt = 0; kt <= qt; kt++) {
        const int buf = kt & 1;
        if (kt < qt) {
            issue_kv(kt + 1, buf ^ 1);
            asm volatile("cp.async.wait_group 1;");
        } else {
            asm volatile("cp.async.wait_group 0;");
        }
        __syncthreads();
        const float* Ks = sm + (1 + 2 * buf) * TSZ;
        const float* Vs = sm + (2 + 2 * buf) * TSZ;
        float s[16];
#pragma unroll
        for (int j = 0; j < 16; j++) s[j] = 0.f;
#pragma unroll 4
        for (int c4 = 0; c4 < 16; c4++) {
            float4 qv = *(const float4*)(Qs + q * APITCH + c4 * 4);
#pragma unroll
            for (int j = 0; j < 16; j++) {
                float4 kv = *(const float4*)(Ks + (sub + 4 * j) * APITCH + c4 * 4);
                s[j] += qv.x * kv.x + qv.y * kv.y + qv.z * kv.z + qv.w * kv.w;
            }
        }
        float tmax = -1e30f;
#pragma unroll
        for (int j = 0; j < 16; j++) {
            int kg = kt * 64 + sub + 4 * j;
            s[j] = (kg <= qglob) ? s[j] * 0.125f : -1e30f;
            tmax = fmaxf(tmax, s[j]);
        }
        tmax = fmaxf(tmax, __shfl_xor_sync(0xffffffff, tmax, 1));
        tmax = fmaxf(tmax, __shfl_xor_sync(0xffffffff, tmax, 2));
        float m_new = fmaxf(m_i, tmax);
        float scale = expf(m_i - m_new);
        float lsum = 0.f;
#pragma unroll
        for (int j = 0; j < 16; j++) {
            float p = expf(s[j] - m_new);
            Ps[q * APITCH + sub + 4 * j] = p;
            lsum += p;
        }
        lsum += __shfl_xor_sync(0xffffffff, lsum, 1);
        lsum += __shfl_xor_sync(0xffffffff, lsum, 2);
        l_i = l_i * scale + lsum;
        m_i = m_new;
        __syncwarp();
#pragma unroll
        for (int i = 0; i < 16; i++) acc[i] *= scale;
#pragma unroll 2
        for (int k4 = 0; k4 < 64; k4 += 4) {
            float4 pv = *(const float4*)(Ps + q * APITCH + k4);
            float pa[4] = {pv.x, pv.y, pv.z, pv.w};
#pragma unroll
            for (int kk = 0; kk < 4; kk++) {
                float p = pa[kk];
#pragma unroll
                for (int c = 0; c < 4; c++) {
                    float4 vv = *(const float4*)(Vs + (k4 + kk) * APITCH + sub * 16 + c * 4);
                    acc[c * 4 + 0] += p * vv.x; acc[c * 4 + 1] += p * vv.y;
                    acc[c * 4 + 2] += p * vv.z; acc[c * 4 + 3] += p * vv.w;
                }
            }
        }
        __syncthreads();
    }
    float inv = 1.f / l_i;
    float* op = O + (size_t)(b * T_ + qglob) * D_ + h * HD_ + sub * 16;
#pragma unroll
    for (int c = 0; c < 4; c++)
        *(float4*)(op + c * 4) = make_float4(acc[c * 4] * inv, acc[c * 4 + 1] * inv,
                                             acc[c * 4 + 2] * inv, acc[c * 4 + 3] * inv);
}

// MoD attention: grid (B*H); Qc [BC][768]; KV [BT][1536]; Oc [BC][768]
__global__ __launch_bounds__(256) void fattn_mod_k(const float* __restrict__ Qc,
                                                   const float* __restrict__ KV,
                                                   const int* __restrict__ cidx,
                                                   float* __restrict__ Oc) {
    extern __shared__ float sm[];
    float* Qs = sm;
    float* Ps = sm + 5 * TSZ;
    int* qpos = (int*)(sm + 6 * TSZ);
    const int bh = blockIdx.x;
    const int b = bh / H_, h = bh % H_;
    const int tid = threadIdx.x;
    if (tid < 64) qpos[tid] = cidx[b * CAP_ + tid] - b * T_;
    for (int i = tid; i < 64 * 16; i += 256) {
        int r = i >> 4, c4 = i & 15;
        *(float4*)(Qs + r * APITCH + c4 * 4) =
            *(const float4*)(Qc + (size_t)(b * CAP_ + r) * D_ + h * HD_ + c4 * 4);
    }
    __syncthreads();
    const int ntiles = (qpos[63] >> 6) + 1;
    const int q = tid >> 2, sub = tid & 3;
    const int myqp = qpos[q];
    int rr_[4], cc_[4];
#pragma unroll
    for (int j = 0; j < 4; j++) { int i = tid + 256 * j; rr_[j] = i >> 4; cc_[j] = i & 15; }

    auto issue_kv = [&](int kt, int buf) {
        float* Kd = sm + (1 + 2 * buf) * TSZ;
        float* Vd = sm + (2 + 2 * buf) * TSZ;
#pragma unroll
        for (int j = 0; j < 4; j++) {
            const float* src = KV + (size_t)(b * T_ + kt * 64 + rr_[j]) * (2 * D_)
                               + h * HD_ + cc_[j] * 4;
            cp_async16(Kd + rr_[j] * APITCH + cc_[j] * 4, src);
            cp_async16(Vd + rr_[j] * APITCH + cc_[j] * 4, src + D_);
        }
        asm volatile("cp.async.commit_group;");
    };

    float m_i = -1e30f, l_i = 0.f;
    float acc[16];
#pragma unroll
    for (int i = 0; i < 16; i++) acc[i] = 0.f;

    issue_kv(0, 0);
    for (int kt = 0; kt < ntiles; kt++) {
        const int buf = kt & 1;
        if (kt + 1 < ntiles) {
            issue_kv(kt + 1, buf ^ 1);
            asm volatile("cp.async.wait_group 1;");
        } else {
            asm volatile("cp.async.wait_group 0;");
        }
        __syncthreads();
        const float* Ks = sm + (1 + 2 * buf) * TSZ;
        const float* Vs = sm + (2 + 2 * buf) * TSZ;
        float s[16];
#pragma unroll
        for (int j = 0; j < 16; j++) s[j] = 0.f;
#pragma unroll 4
        for (int c4 = 0; c4 < 16; c4++) {
            float4 qv = *(const float4*)(Qs + q * APITCH + c4 * 4);
#pragma unroll
            for (int j = 0; j < 16; j++) {
                float4 kv = *(const float4*)(Ks + (sub + 4 * j) * APITCH + c4 * 4);
                s[j] += qv.x * kv.x + qv.y * kv.y + qv.z * kv.z + qv.w * kv.w;
            }
        }
        float tmax = -1e30f;
#pragma unroll
        for (int j = 0; j < 16; j++) {
            int kg = kt * 64 + sub + 4 * j;
            s[j] = (kg <= myqp) ? s[j] * 0.125f : -1e30f;
            tmax = fmaxf(tmax, s[j]);
        }
        tmax = fmaxf(tmax, __shfl_xor_sync(0xffffffff, tmax, 1));
        tmax = fmaxf(tmax, __shfl_xor_sync(0xffffffff, tmax, 2));
        float m_new = fmaxf(m_i, tmax);
        if (m_new > -1e30f) {
            float scale = expf(m_i - m_new);
            float lsum = 0.f;
#pragma unroll
            for (int j = 0; j < 16; j++) {
                float p = expf(s[j] - m_new);
                Ps[q * APITCH + sub + 4 * j] = p;
                lsum += p;
            }
            lsum += __shfl_xor_sync(0xffffffff, lsum, 1);
            lsum += __shfl_xor_sync(0xffffffff, lsum, 2);
            l_i = l_i * scale + lsum;
            m_i = m_new;
            __syncwarp();
#pragma unroll
            for (int i = 0; i < 16; i++) acc[i] *= scale;
#pragma unroll 2
            for (int k4 = 0; k4 < 64; k4 += 4) {
                float4 pv = *(const float4*)(Ps + q * APITCH + k4);
                float pa[4] = {pv.x, pv.y, pv.z, pv.w};
#pragma unroll
                for (int kk = 0; kk < 4; kk++) {
                    float p = pa[kk];
#pragma unroll
                    for (int c = 0; c < 4; c++) {
                        float4 vv = *(const float4*)(Vs + (k4 + kk) * APITCH + sub * 16 + c * 4);
                        acc[c * 4 + 0] += p * vv.x; acc[c * 4 + 1] += p * vv.y;
                        acc[c * 4 + 2] += p * vv.z; acc[c * 4 + 3] += p * vv.w;
                    }
                }
            }
        }
        __syncthreads();
    }
    float inv = 1.f / l_i;
    float* op = Oc + (size_t)(b * CAP_ + q) * D_ + h * HD_ + sub * 16;
#pragma unroll
    for (int c = 0; c < 4; c++)
        *(float4*)(op + c * 4) = make_float4(acc[c * 4] * inv, acc[c * 4 + 1] * inv,
                                             acc[c * 4 + 2] * inv, acc[c * 4 + 3] * inv);
}

// ------------------- elementwise / small kernels -------------------
__global__ void embed_k(const int* __restrict__ ids, const float* __restrict__ E,
                        const float* __restrict__ Pw, float* __restrict__ X) {
    int m = blockIdx.x;
    int t = m % T_;
    int id = ids[m];
    for (int i = threadIdx.x; i < D_; i += 256)
        X[(size_t)m * D_ + i] = E[(size_t)id * D_ + i] + Pw[(size_t)t * D_ + i];
}

__global__ void rmsnorm_k(const float* __restrict__ X, const float* __restrict__ w,
                          float* __restrict__ Yb) {
    int m = blockIdx.x;
    const float* x = X + (size_t)m * D_;
    float s = 0.f;
    for (int i = threadIdx.x; i < D_; i += 256) { float v = x[i]; s += v * v; }
    __shared__ float red[256];
    red[threadIdx.x] = s; __syncthreads();
    for (int st = 128; st > 0; st >>= 1) {
        if (threadIdx.x < st) red[threadIdx.x] += red[threadIdx.x + st];
        __syncthreads();
    }
    float scale = rsqrtf(red[0] / (float)D_ + 1e-6f);
    for (int i = threadIdx.x; i < D_; i += 256)
        Yb[(size_t)m * D_ + i] = x[i] * scale * w[i];
}

__global__ void router_score_k(const float* __restrict__ X, const float* __restrict__ rw,
                               float* __restrict__ sc) {
    int m = blockIdx.x;
    float s = 0.f;
    for (int i = threadIdx.x; i < D_; i += 256) s += X[(size_t)m * D_ + i] * rw[i];
    __shared__ float red[256];
    red[threadIdx.x] = s; __syncthreads();
    for (int st = 128; st > 0; st >>= 1) {
        if (threadIdx.x < st) red[threadIdx.x] += red[threadIdx.x + st];
        __syncthreads();
    }
    if (threadIdx.x == 0) sc[m] = red[0];
}

__global__ void topk_cidx_k(const float* __restrict__ sc, int* __restrict__ cidx) {
    int b = blockIdx.x, t = threadIdx.x;  // 512 threads
    __shared__ float s[T_];
    __shared__ int flag[T_];
    s[t] = sc[b * T_ + t];
    __syncthreads();
    float mine = s[t];
    int rank = 0;
    for (int j = 0; j < T_; j++) {
        float v = s[j];
        if (v > mine || (v == mine && j < t)) rank++;
    }
    int selected = (rank < CAP_) ? 1 : 0;
    flag[t] = selected;
    __syncthreads();
    if (selected) {
        int pos = 0;
        for (int j = 0; j < t; j++) pos += flag[j];
        cidx[b * CAP_ + pos] = b * T_ + t;
    }
}

__global__ void gather_k(const float* __restrict__ X, const int* __restrict__ cidx,
                         float* __restrict__ Yc) {
    int i = blockIdx.x;
    int row = cidx[i];
    for (int d = threadIdx.x; d < D_; d += 256)
        Yc[(size_t)i * D_ + d] = X[(size_t)row * D_ + d];
}

__global__ void scatter_k(const float* __restrict__ Yc, const int* __restrict__ cidx,
                          float* __restrict__ X) {
    int i = blockIdx.x;
    int row = cidx[i];
    for (int d = threadIdx.x; d < D_; d += 256)
        X[(size_t)row * D_ + d] = Yc[(size_t)i * D_ + d];
}

__global__ void memtopk_k(const float* __restrict__ SIM, const float* __restrict__ MV,
                          float* __restrict__ RETP) {
    int m = blockIdx.x;
    int tid = threadIdx.x;  // 256
    __shared__ float s[NMEM_];
    __shared__ float wts[TOPK_];
    __shared__ int idxs[TOPK_];
    __shared__ float rv[256];
    __shared__ int ri[256];
    const float invs = 0.03608439182435161f;  // 1/sqrt(768)
    for (int i = tid; i < NMEM_; i += 256) s[i] = SIM[(size_t)m * NMEM_ + i] * invs;
    __syncthreads();
    for (int j = 0; j < TOPK_; j++) {
        float bv = -1e30f; int bi = 0x7fffffff;
        for (int i = tid; i < NMEM_; i += 256) {
            if (s[i] > bv) { bv = s[i]; bi = i; }
        }
        rv[tid] = bv; ri[tid] = bi; __syncthreads();
        for (int st = 128; st > 0; st >>= 1) {
            if (tid < st) {
                if (rv[tid + st] > rv[tid] ||
                    (rv[tid + st] == rv[tid] && ri[tid + st] < ri[tid])) {
                    rv[tid] = rv[tid + st]; ri[tid] = ri[tid + st];
                }
            }
            __syncthreads();
        }
        if (tid == 0) { wts[j] = rv[0]; idxs[j] = ri[0]; s[ri[0]] = -1e30f; }
        __syncthreads();
    }
    if (tid == 0) {
        float mx = wts[0];
        float sum = 0.f;
        for (int j = 0; j < TOPK_; j++) { wts[j] = expf(wts[j] - mx); sum += wts[j]; }
        float inv = 1.f / sum;
        for (int j = 0; j < TOPK_; j++) wts[j] *= inv;
    }
    __syncthreads();
    for (int i = tid; i < D_; i += 256) {
        float a = 0.f;
#pragma unroll
        for (int j = 0; j < TOPK_; j++) a += wts[j] * MV[(size_t)idxs[j] * D_ + i];
        RETP[(size_t)m * D_ + i] = a;
    }
}

__global__ void concat_k(const float* __restrict__ X, const float* __restrict__ RET,
                         float* __restrict__ GI) {
    int m = blockIdx.x;
    for (int i = threadIdx.x; i < D_; i += 256) {
        GI[(size_t)m * 2 * D_ + i] = X[(size_t)m * D_ + i];
        GI[(size_t)m * 2 * D_ + D_ + i] = RET[(size_t)m * D_ + i];
    }
}

__global__ void gelu_bias_k(float* __restrict__ H1, const float* __restrict__ b1, int n) {
    int i = blockIdx.x * blockDim.x + threadIdx.x;
    if (i < n) {
        int col = i % (D_ / 2);
        float v = H1[i] + b1[col];
        H1[i] = 0.5f * v * (1.f + erff(v * 0.70710678118654752f));
    }
}

__global__ void gate_k(const float* __restrict__ H1, const float* __restrict__ w2,
                       const float* __restrict__ b2, const float* __restrict__ RET,
                       float* __restrict__ X) {
    int m = blockIdx.x;
    float s = 0.f;
    for (int i = threadIdx.x; i < D_ / 2; i += 256)
        s += H1[(size_t)m * (D_ / 2) + i] * w2[i];
    __shared__ float red[256];
    red[threadIdx.x] = s; __syncthreads();
    for (int st = 128; st > 0; st >>= 1) {
        if (threadIdx.x < st) red[threadIdx.x] += red[threadIdx.x + st];
        __syncthreads();
    }
    __shared__ float gsh;
    if (threadIdx.x == 0) gsh = 1.f / (1.f + expf(-(red[0] + b2[0])));
    __syncthreads();
    float g = gsh;
    for (int i = threadIdx.x; i < D_; i += 256)
        X[(size_t)m * D_ + i] += g * RET[(size_t)m * D_ + i];
}

// ------------------- host orchestration -------------------
static void gemm(const float* A, const float* Bw, float* C, int M, int N, int K, bool acc) {
    dim3 grid((N + 127) / 128, M / 128);
    if (N % 128 == 0) {
        if (acc) mmah_gemm_nt<true, false, false, 3><<<grid, 256>>>(A, nullptr, Bw, C, M, N, K);
        else     mmah_gemm_nt<false, false, false, 3><<<grid, 256>>>(A, nullptr, Bw, C, M, N, K);
    } else {
        if (acc) mmah_gemm_nt<true, true, false, 3><<<grid, 256>>>(A, nullptr, Bw, C, M, N, K);
        else     mmah_gemm_nt<false, true, false, 3><<<grid, 256>>>(A, nullptr, Bw, C, M, N, K);
    }
}

static void gemm_swiglu(const float* U, const float* V2, const float* Bw, float* C,
                        int M, int N, int K) {
    dim3 grid(N / 128, M / 128);
    mmah_gemm_nt<true, false, true, 3><<<grid, 256>>>(U, V2, Bw, C, M, N, K);
}

static void gemm_lm(const float* A, const float* Bw, float* C, int M, int N, int K) {
    dim3 grid((N + 127) / 128, M / 128);
    mmah_gemm_nt<false, true, false, 2><<<grid, 256>>>(A, nullptr, Bw, C, M, N, K);
}

struct Ptrs {
    float *X, *Y, *Hb, *QKV, *ATT, *U, *V2, *SIM, *RETP, *RET, *GI, *H1, *SC;
    int* CIDX;
};

static void tblock_full(const Ptrs& p, const float* qkv_w, const float* out_w,
                        const float* n1, const float* n2, const float* w1,
                        const float* w2, const float* w3, float* x) {
    rmsnorm_k<<<BT_, 256>>>(x, n1, p.Hb);
    gemm(p.Hb, qkv_w, p.QKV, BT_, QKVD_, D_, false);
    fattn_k<<<dim3(T_ / 64, B_ * H_), 256, FA_SMEM>>>(p.QKV, p.ATT);
    gemm(p.ATT, out_w, x, BT_, D_, D_, true);
    rmsnorm_k<<<BT_, 256>>>(x, n2, p.Hb);
    gemm(p.Hb, w1, p.U, BT_, DFF_, D_, false);
    gemm(p.Hb, w2, p.V2, BT_, DFF_, D_, false);
    gemm_swiglu(p.U, p.V2, w3, x, BT_, D_, DFF_);
    (void)0;
}

static void tblock_mod(const Ptrs& p, const float* qkv_w, const float* out_w,
                       const float* n1, const float* n2, const float* w1,
                       const float* w2, const float* w3, const float* rw) {
    float* KV = p.QKV;
    float* Qc = p.QKV + (size_t)BT_ * (2 * D_);
    float* Xc = p.Y;
    float* Hc = p.RETP;
    float* Oc = p.ATT;

    router_score_k<<<BT_, 256>>>(p.X, rw, p.SC);
    topk_cidx_k<<<B_, T_>>>(p.SC, p.CIDX);
    rmsnorm_k<<<BT_, 256>>>(p.X, n1, p.Hb);
    gemm(p.Hb, qkv_w + (size_t)D_ * D_, KV, BT_, 2 * D_, D_, false);
    gather_k<<<BC_, 256>>>(p.Hb, p.CIDX, Hc);
    gemm(Hc, qkv_w, Qc, BC_, D_, D_, false);
    fattn_mod_k<<<B_ * H_, 256, FAM_SMEM>>>(Qc, KV, p.CIDX, Oc);
    gather_k<<<BC_, 256>>>(p.X, p.CIDX, Xc);
    gemm(Oc, out_w, Xc, BC_, D_, D_, true);
    rmsnorm_k<<<BC_, 256>>>(Xc, n2, Hc);
    gemm(Hc, w1, p.U, BC_, DFF_, D_, false);
    gemm(Hc, w2, p.V2, BC_, DFF_, D_, false);
    gemm_swiglu(p.U, p.V2, w3, Xc, BC_, D_, DFF_);
    scatter_k<<<BC_, 256>>>(Xc, p.CIDX, p.X);
}

extern "C" void kernel_launch(void* const* d_in, const int* in_sizes, int n_in,
                              void* d_out, int out_size) {
    const int*   ids       = (const int*)d_in[0];
    const float* embed_w   = (const float*)d_in[1];
    const float* pos_w     = (const float*)d_in[2];
    const float* qkv_w     = (const float*)d_in[3];
    const float* out_w     = (const float*)d_in[4];
    const float* norm1_w   = (const float*)d_in[5];
    const float* norm2_w   = (const float*)d_in[6];
    const float* ff_w1     = (const float*)d_in[7];
    const float* ff_w2     = (const float*)d_in[8];
    const float* ff_w3     = (const float*)d_in[9];
    const float* router_w  = (const float*)d_in[10];
    const float* lat_qkv_w = (const float*)d_in[11];
    const float* lat_out_w = (const float*)d_in[12];
    const float* lat_n1    = (const float*)d_in[13];
    const float* lat_n2    = (const float*)d_in[14];
    const float* lat_w1    = (const float*)d_in[15];
    const float* lat_w2    = (const float*)d_in[16];
    const float* lat_w3    = (const float*)d_in[17];
    const float* mem_keys  = (const float*)d_in[18];
    const float* mem_values= (const float*)d_in[19];
    const float* mem_qp    = (const float*)d_in[20];
    const float* mem_op    = (const float*)d_in[21];
    const float* gate_w1   = (const float*)d_in[22];
    const float* gate_b1   = (const float*)d_in[23];
    const float* gate_w2   = (const float*)d_in[24];
    const float* gate_b2   = (const float*)d_in[25];
    const float* final_nw  = (const float*)d_in[26];
    float* out = (float*)d_out;

    static bool attr_done = false;
    if (!attr_done) {
        cudaFuncSetAttribute(fattn_k, cudaFuncAttributeMaxDynamicSharedMemorySize, FA_SMEM);
        cudaFuncSetAttribute(fattn_mod_k, cudaFuncAttributeMaxDynamicSharedMemorySize, FAM_SMEM);
        cudaFuncSetAttribute(fattn_k, cudaFuncAttributePreferredSharedMemoryCarveout, 100);
        cudaFuncSetAttribute(fattn_mod_k, cudaFuncAttributePreferredSharedMemoryCarveout, 100);
        attr_done = true;
    }

    Ptrs p;
    cudaGetSymbolAddress((void**)&p.X, g_X);
    cudaGetSymbolAddress((void**)&p.Y, g_Y);
    cudaGetSymbolAddress((void**)&p.Hb, g_Hb);
    cudaGetSymbolAddress((void**)&p.QKV, g_QKV);
    cudaGetSymbolAddress((void**)&p.ATT, g_ATT);
    cudaGetSymbolAddress((void**)&p.U, g_U);
    cudaGetSymbolAddress((void**)&p.V2, g_V2);
    cudaGetSymbolAddress((void**)&p.SIM, g_SIM);
    cudaGetSymbolAddress((void**)&p.RETP, g_RETP);
    cudaGetSymbolAddress((void**)&p.RET, g_RET);
    cudaGetSymbolAddress((void**)&p.GI, g_GI);
    cudaGetSymbolAddress((void**)&p.H1, g_H1);
    cudaGetSymbolAddress((void**)&p.SC, g_SC);
    cudaGetSymbolAddress((void**)&p.CIDX, g_CIDX);

    embed_k<<<BT_, 256>>>(ids, embed_w, pos_w, p.X);

    for (int i = 0; i < L_; i++) {
        const float* qw = qkv_w + (size_t)i * QKVD_ * D_;
        const float* ow = out_w + (size_t)i * D_ * D_;
        const float* n1 = norm1_w + (size_t)i * D_;
        const float* n2 = norm2_w + (size_t)i * D_;
        const float* w1 = ff_w1 + (size_t)i * DFF_ * D_;
        const float* w2 = ff_w2 + (size_t)i * DFF_ * D_;
        const float* w3 = ff_w3 + (size_t)i * D_ * DFF_;
        if (i % 2 == 1)
            tblock_mod(p, qw, ow, n1, n2, w1, w2, w3, router_w + (size_t)i * D_);
        else
            tblock_full(p, qw, ow, n1, n2, w1, w2, w3, p.X);
    }

    for (int it = 0; it < NLAT_; it++)
        tblock_full(p, lat_qkv_w, lat_out_w, lat_n1, lat_n2, lat_w1, lat_w2, lat_w3, p.X);

    // kNN memory retrieval
    gemm(p.X, mem_qp, p.Hb, BT_, D_, D_, false);
    gemm(p.Hb, mem_keys, p.SIM, BT_, NMEM_, D_, false);
    memtopk_k<<<BT_, 256>>>(p.SIM, mem_values, p.RETP);
    gemm(p.RETP, mem_op, p.RET, BT_, D_, D_, false);
    concat_k<<<BT_, 256>>>(p.X, p.RET, p.GI);
    gemm(p.GI, gate_w1, p.H1, BT_, D_ / 2, 2 * D_, false);
    gelu_bias_k<<<(BT_ * (D_ / 2) + 255) / 256, 256>>>(p.H1, gate_b1, BT_ * (D_ / 2));
    gate_k<<<BT_, 256>>>(p.H1, gate_w2, gate_b2, p.RET, p.X);

    // final norm + tied LM head (2-term split: no downstream selections)
    rmsnorm_k<<<BT_, 256>>>(p.X, final_nw, p.Hb);
    gemm_lm(p.Hb, embed_w, out, BT_, VOCAB_, D_);
}

// round 17
// speedup vs baseline: 1.0595x; 1.0595x over previous
#include <cuda_runtime.h>
#include <cuda_bf16.h>
#include <cuda_fp16.h>
#include <math.h>
#include <stdint.h>

#define B_ 4
#define T_ 512
#define D_ 768
#define H_ 12
#define HD_ 64
#define L_ 12
#define DFF_ 2048
#define VOCAB_ 50257
#define NMEM_ 1024
#define TOPK_ 8
#define NLAT_ 4
#define CAP_ 64
#define BT_ (B_*T_)
#define QKVD_ (3*D_)
#define BC_ (B_*CAP_)   // 256 compacted rows

// ------------------- scratch (device globals; no allocation) -------------------
__device__ float g_X[BT_*D_];
__device__ float g_Y[BT_*D_];
__device__ float g_Hb[BT_*D_];
__device__ float g_QKV[BT_*QKVD_];
__device__ float g_ATT[BT_*D_];
__device__ float g_U[BT_*DFF_];
__device__ float g_V2[BT_*DFF_];
__device__ float g_SIM[BT_*NMEM_];
__device__ float g_RETP[BT_*D_];
__device__ float g_RET[BT_*D_];
__device__ float g_GI[BT_*2*D_];
__device__ float g_H1[BT_*(D_/2)];
__device__ float g_SC[BT_];
__device__ int   g_CIDX[BT_];

// ==================== 3x-split FP16 mma.sync GEMM (m16n8k16) ====================
#define PITCH2 12
#define TILE_U (128 * PITCH2)

__device__ __forceinline__ uint32_t pkh(__half a, __half b) {
    __half2 h = __halves2half2(a, b);
    return *(uint32_t*)&h;
}

__device__ __forceinline__ void mma_f16(float* c, uint32_t a0, uint32_t a1,
                                        uint32_t a2, uint32_t a3,
                                        uint32_t b0, uint32_t b1) {
    asm volatile(
        "mma.sync.aligned.m16n8k16.row.col.f32.f16.f16.f32 "
        "{%0,%1,%2,%3}, {%4,%5,%6,%7}, {%8,%9}, {%0,%1,%2,%3};"
        : "+f"(c[0]), "+f"(c[1]), "+f"(c[2]), "+f"(c[3])
        : "r"(a0), "r"(a1), "r"(a2), "r"(a3), "r"(b0), "r"(b1));
}

// TERMS: 3 = full split, 2 = drop ah*bl (weight-lo) term — LM head only.
template<bool ACC, bool NGUARD, int TERMS>
__global__ __launch_bounds__(256, 2) void mmah_gemm_nt(const float* __restrict__ A,
                                                       const float* __restrict__ Bw,
                                                       float* __restrict__ C,
                                                       int M, int N, int K) {
    __shared__ uint32_t smu[2 * 4 * TILE_U];
    const int bm = blockIdx.y * 128, bn = blockIdx.x * 128;
    const int tid = threadIdx.x;
    const int wid = tid >> 5, lane = tid & 31;
    const int warp_m = wid >> 2, warp_n = wid & 3;
    const int g = lane >> 2, tg = lane & 3;

    float acc[4][4][4];
#pragma unroll
    for (int mi = 0; mi < 4; mi++)
#pragma unroll
        for (int ni = 0; ni < 4; ni++)
#pragma unroll
            for (int e = 0; e < 4; e++) acc[mi][ni][e] = 0.f;

    const int r_0 = tid >> 2,         c4_0 = (tid & 3);
    const int r_1 = (tid + 256) >> 2, c4_1 = ((tid + 256) & 3);
    const float* a0p = A + (size_t)(bm + r_0) * K + c4_0 * 4;
    const float* a1p = A + (size_t)(bm + r_1) * K + c4_1 * 4;
    const bool b0ok = !NGUARD || (bn + r_0) < N;
    const bool b1ok = !NGUARD || (bn + r_1) < N;
    const float* b0p = Bw + (size_t)(bn + r_0) * K + c4_0 * 4;
    const float* b1p = Bw + (size_t)(bn + r_1) * K + c4_1 * 4;

    const int nt = K >> 4;
    float4 ra0, ra1, rb0, rb1;

    ra0 = *(const float4*)(a0p);
    ra1 = *(const float4*)(a1p);
    rb0 = b0ok ? *(const float4*)(b0p) : make_float4(0.f, 0.f, 0.f, 0.f);
    rb1 = b1ok ? *(const float4*)(b1p) : make_float4(0.f, 0.f, 0.f, 0.f);

    for (int t = 0; t < nt; t++) {
        const int s = t & 1;
        uint32_t* st = smu + s * 4 * TILE_U;
        {
            auto put = [&](uint32_t* tH, uint32_t* tL, int r, int c4, float4 v) {
                __half hx = __float2half_rn(v.x), hy = __float2half_rn(v.y);
                __half hz = __float2half_rn(v.z), hw = __float2half_rn(v.w);
                uint32_t h0 = pkh(hx, hy), h1 = pkh(hz, hw);
                uint32_t l0 = pkh(__float2half_rn(v.x - __half2float(hx)),
                                  __float2half_rn(v.y - __half2float(hy)));
                uint32_t l1 = pkh(__float2half_rn(v.z - __half2float(hz)),
                                  __float2half_rn(v.w - __half2float(hw)));
                int idx = r * PITCH2 + c4 * 2;
                *(uint2*)&tH[idx] = make_uint2(h0, h1);
                *(uint2*)&tL[idx] = make_uint2(l0, l1);
            };
            put(st,              st + TILE_U,     r_0, c4_0, ra0);
            put(st,              st + TILE_U,     r_1, c4_1, ra1);
            put(st + 2 * TILE_U, st + 3 * TILE_U, r_0, c4_0, rb0);
            put(st + 2 * TILE_U, st + 3 * TILE_U, r_1, c4_1, rb1);
        }
        if (t + 1 < nt) {
            const int k0 = (t + 1) << 4;
            ra0 = *(const float4*)(a0p + k0);
            ra1 = *(const float4*)(a1p + k0);
            rb0 = b0ok ? *(const float4*)(b0p + k0) : make_float4(0.f, 0.f, 0.f, 0.f);
            rb1 = b1ok ? *(const float4*)(b1p + k0) : make_float4(0.f, 0.f, 0.f, 0.f);
        }
        __syncthreads();

        const uint32_t* Ah = smu + s * 4 * TILE_U;
        const uint32_t* Al = Ah + TILE_U;
        const uint32_t* Bh = Ah + 2 * TILE_U;
        const uint32_t* Bl = Ah + 3 * TILE_U;

        uint32_t bh[4][2], bl[4][2];
#pragma unroll
        for (int ni = 0; ni < 4; ni++) {
            const int rb = (warp_n * 32 + ni * 8 + g) * PITCH2 + tg;
            bh[ni][0] = Bh[rb]; bh[ni][1] = Bh[rb + 4];
            if (TERMS == 3) { bl[ni][0] = Bl[rb]; bl[ni][1] = Bl[rb + 4]; }
        }
#pragma unroll
        for (int mi = 0; mi < 4; mi++) {
            const int ra = (warp_m * 64 + mi * 16 + g) * PITCH2 + tg;
            const uint32_t ah0 = Ah[ra], ah1 = Ah[ra + 8 * PITCH2];
            const uint32_t ah2 = Ah[ra + 4], ah3 = Ah[ra + 8 * PITCH2 + 4];
            const uint32_t al0 = Al[ra], al1 = Al[ra + 8 * PITCH2];
            const uint32_t al2 = Al[ra + 4], al3 = Al[ra + 8 * PITCH2 + 4];
#pragma unroll
            for (int ni = 0; ni < 4; ni++) {
                mma_f16(acc[mi][ni], al0, al1, al2, al3, bh[ni][0], bh[ni][1]);
                if (TERMS == 3)
                    mma_f16(acc[mi][ni], ah0, ah1, ah2, ah3, bl[ni][0], bl[ni][1]);
                mma_f16(acc[mi][ni], ah0, ah1, ah2, ah3, bh[ni][0], bh[ni][1]);
            }
        }
    }

#pragma unroll
    for (int mi = 0; mi < 4; mi++) {
#pragma unroll
        for (int ni = 0; ni < 4; ni++) {
            int row0 = bm + warp_m * 64 + mi * 16 + g;
            int col = bn + warp_n * 32 + ni * 8 + tg * 2;
#pragma unroll
            for (int rr = 0; rr < 2; rr++) {
                int row = row0 + rr * 8;
                float* cp = C + (size_t)row * N + col;
                float v0 = acc[mi][ni][rr * 2 + 0];
                float v1 = acc[mi][ni][rr * 2 + 1];
                if (!NGUARD || col + 1 < N) {
                    if (ACC) { cp[0] += v0; cp[1] += v1; }
                    else     { cp[0] = v0;  cp[1] = v1; }
                } else if (col < N) {
                    if (ACC) cp[0] += v0; else cp[0] = v0;
                }
            }
        }
    }
}

// ==================== fused flash-style attention (register K/V prefetch) ========
#define APITCH 68
#define FA_SMEM (4 * 64 * APITCH * 4)
#define FAM_SMEM (FA_SMEM + 64 * 4)

// Full attention: grid (T/64, B*H); QKV [BT][2304]; O [BT][768]
__global__ __launch_bounds__(256) void fattn_k(const float* __restrict__ QKV,
                                               float* __restrict__ O) {
    extern __shared__ float sm[];
    float* Qs = sm;
    float* Ks = sm + 64 * APITCH;
    float* Vs = sm + 2 * 64 * APITCH;
    float* Ps = sm + 3 * 64 * APITCH;
    const int qt = gridDim.x - 1 - blockIdx.x;  // long blocks first
    const int bh = blockIdx.y;
    const int b = bh / H_, h = bh % H_;
    const int tid = threadIdx.x;
    const int q0 = qt * 64;
    for (int i = tid; i < 64 * 16; i += 256) {
        int r = i >> 4, c4 = i & 15;
        *(float4*)(Qs + r * APITCH + c4 * 4) =
            *(const float4*)(QKV + (size_t)(b * T_ + q0 + r) * QKVD_ + h * HD_ + c4 * 4);
    }
    const int q = tid >> 2, sub = tid & 3;
    const int qglob = q0 + q;
    int rr_[4], cc_[4];
#pragma unroll
    for (int j = 0; j < 4; j++) { int i = tid + 256 * j; rr_[j] = i >> 4; cc_[j] = i & 15; }
    float4 kreg[4], vreg[4];
#pragma unroll
    for (int j = 0; j < 4; j++) {
        const float* src = QKV + (size_t)(b * T_ + rr_[j]) * QKVD_ + h * HD_ + cc_[j] * 4;
        kreg[j] = *(const float4*)(src + D_);
        vreg[j] = *(const float4*)(src + 2 * D_);
    }
    float m_i = -1e30f, l_i = 0.f;
    float acc[16];
#pragma unroll
    for (int i = 0; i < 16; i++) acc[i] = 0.f;

    for (int kt = 0; kt <= qt; kt++) {
        __syncthreads();
#pragma unroll
        for (int j = 0; j < 4; j++) {
            *(float4*)(Ks + rr_[j] * APITCH + cc_[j] * 4) = kreg[j];
            *(float4*)(Vs + rr_[j] * APITCH + cc_[j] * 4) = vreg[j];
        }
        __syncthreads();
        if (kt < qt) {
#pragma unroll
            for (int j = 0; j < 4; j++) {
                const float* src = QKV + (size_t)(b * T_ + (kt + 1) * 64 + rr_[j]) * QKVD_
                                   + h * HD_ + cc_[j] * 4;
                kreg[j] = *(const float4*)(src + D_);
                vreg[j] = *(const float4*)(src + 2 * D_);
            }
        }
        float s[16];
#pragma unroll
        for (int j = 0; j < 16; j++) s[j] = 0.f;
#pragma unroll 4
        for (int c4 = 0; c4 < 16; c4++) {
            float4 qv = *(const float4*)(Qs + q * APITCH + c4 * 4);
#pragma unroll
            for (int j = 0; j < 16; j++) {
                float4 kv = *(const float4*)(Ks + (sub + 4 * j) * APITCH + c4 * 4);
                s[j] += qv.x * kv.x + qv.y * kv.y + qv.z * kv.z + qv.w * kv.w;
            }
        }
        float tmax = -1e30f;
#pragma unroll
        for (int j = 0; j < 16; j++) {
            int kg = kt * 64 + sub + 4 * j;
            s[j] = (kg <= qglob) ? s[j] * 0.125f : -1e30f;
            tmax = fmaxf(tmax, s[j]);
        }
        tmax = fmaxf(tmax, __shfl_xor_sync(0xffffffff, tmax, 1));
        tmax = fmaxf(tmax, __shfl_xor_sync(0xffffffff, tmax, 2));
        float m_new = fmaxf(m_i, tmax);
        float scale = expf(m_i - m_new);
        float lsum = 0.f;
#pragma unroll
        for (int j = 0; j < 16; j++) {
            float p = expf(s[j] - m_new);
            Ps[q * APITCH + sub + 4 * j] = p;
            lsum += p;
        }
        lsum += __shfl_xor_sync(0xffffffff, lsum, 1);
        lsum += __shfl_xor_sync(0xffffffff, lsum, 2);
        l_i = l_i * scale + lsum;
        m_i = m_new;
        __syncwarp();
#pragma unroll
        for (int i = 0; i < 16; i++) acc[i] *= scale;
#pragma unroll 2
        for (int k4 = 0; k4 < 64; k4 += 4) {
            float4 pv = *(const float4*)(Ps + q * APITCH + k4);
            float pa[4] = {pv.x, pv.y, pv.z, pv.w};
#pragma unroll
            for (int kk = 0; kk < 4; kk++) {
                float p = pa[kk];
#pragma unroll
                for (int c = 0; c < 4; c++) {
                    float4 vv = *(const float4*)(Vs + (k4 + kk) * APITCH + sub * 16 + c * 4);
                    acc[c * 4 + 0] += p * vv.x; acc[c * 4 + 1] += p * vv.y;
                    acc[c * 4 + 2] += p * vv.z; acc[c * 4 + 3] += p * vv.w;
                }
            }
        }
    }
    float inv = 1.f / l_i;
    float* op = O + (size_t)(b * T_ + qglob) * D_ + h * HD_ + sub * 16;
#pragma unroll
    for (int c = 0; c < 4; c++)
        *(float4*)(op + c * 4) = make_float4(acc[c * 4] * inv, acc[c * 4 + 1] * inv,
                                             acc[c * 4 + 2] * inv, acc[c * 4 + 3] * inv);
}

// MoD attention: grid (B*H); Qc [BC][768]; KV [BT][1536]; Oc [BC][768]
__global__ __launch_bounds__(256) void fattn_mod_k(const float* __restrict__ Qc,
                                                   const float* __restrict__ KV,
                                                   const int* __restrict__ cidx,
                                                   float* __restrict__ Oc) {
    extern __shared__ float sm[];
    float* Qs = sm;
    float* Ks = sm + 64 * APITCH;
    float* Vs = sm + 2 * 64 * APITCH;
    float* Ps = sm + 3 * 64 * APITCH;
    int* qpos = (int*)(sm + 4 * 64 * APITCH);
    const int bh = blockIdx.x;
    const int b = bh / H_, h = bh % H_;
    const int tid = threadIdx.x;
    if (tid < 64) qpos[tid] = cidx[b * CAP_ + tid] - b * T_;
    for (int i = tid; i < 64 * 16; i += 256) {
        int r = i >> 4, c4 = i & 15;
        *(float4*)(Qs + r * APITCH + c4 * 4) =
            *(const float4*)(Qc + (size_t)(b * CAP_ + r) * D_ + h * HD_ + c4 * 4);
    }
    __syncthreads();
    const int ntiles = (qpos[63] >> 6) + 1;
    const int q = tid >> 2, sub = tid & 3;
    const int myqp = qpos[q];
    int rr_[4], cc_[4];
#pragma unroll
    for (int j = 0; j < 4; j++) { int i = tid + 256 * j; rr_[j] = i >> 4; cc_[j] = i & 15; }
    float4 kreg[4], vreg[4];
#pragma unroll
    for (int j = 0; j < 4; j++) {
        const float* src = KV + (size_t)(b * T_ + rr_[j]) * (2 * D_) + h * HD_ + cc_[j] * 4;
        kreg[j] = *(const float4*)(src);
        vreg[j] = *(const float4*)(src + D_);
    }
    float m_i = -1e30f, l_i = 0.f;
    float acc[16];
#pragma unroll
    for (int i = 0; i < 16; i++) acc[i] = 0.f;

    for (int kt = 0; kt < ntiles; kt++) {
        __syncthreads();
#pragma unroll
        for (int j = 0; j < 4; j++) {
            *(float4*)(Ks + rr_[j] * APITCH + cc_[j] * 4) = kreg[j];
            *(float4*)(Vs + rr_[j] * APITCH + cc_[j] * 4) = vreg[j];
        }
        __syncthreads();
        if (kt + 1 < ntiles) {
#pragma unroll
            for (int j = 0; j < 4; j++) {
                const float* src = KV + (size_t)(b * T_ + (kt + 1) * 64 + rr_[j]) * (2 * D_)
                                   + h * HD_ + cc_[j] * 4;
                kreg[j] = *(const float4*)(src);
                vreg[j] = *(const float4*)(src + D_);
            }
        }
        float s[16];
#pragma unroll
        for (int j = 0; j < 16; j++) s[j] = 0.f;
#pragma unroll 4
        for (int c4 = 0; c4 < 16; c4++) {
            float4 qv = *(const float4*)(Qs + q * APITCH + c4 * 4);
#pragma unroll
            for (int j = 0; j < 16; j++) {
                float4 kv = *(const float4*)(Ks + (sub + 4 * j) * APITCH + c4 * 4);
                s[j] += qv.x * kv.x + qv.y * kv.y + qv.z * kv.z + qv.w * kv.w;
            }
        }
        float tmax = -1e30f;
#pragma unroll
        for (int j = 0; j < 16; j++) {
            int kg = kt * 64 + sub + 4 * j;
            s[j] = (kg <= myqp) ? s[j] * 0.125f : -1e30f;
            tmax = fmaxf(tmax, s[j]);
        }
        tmax = fmaxf(tmax, __shfl_xor_sync(0xffffffff, tmax, 1));
        tmax = fmaxf(tmax, __shfl_xor_sync(0xffffffff, tmax, 2));
        float m_new = fmaxf(m_i, tmax);
        if (m_new > -1e30f) {
            float scale = expf(m_i - m_new);
            float lsum = 0.f;
#pragma unroll
            for (int j = 0; j < 16; j++) {
                float p = expf(s[j] - m_new);
                Ps[q * APITCH + sub + 4 * j] = p;
                lsum += p;
            }
            lsum += __shfl_xor_sync(0xffffffff, lsum, 1);
            lsum += __shfl_xor_sync(0xffffffff, lsum, 2);
            l_i = l_i * scale + lsum;
            m_i = m_new;
            __syncwarp();
#pragma unroll
            for (int i = 0; i < 16; i++) acc[i] *= scale;
#pragma unroll 2
            for (int k4 = 0; k4 < 64; k4 += 4) {
                float4 pv = *(const float4*)(Ps + q * APITCH + k4);
                float pa[4] = {pv.x, pv.y, pv.z, pv.w};
#pragma unroll
                for (int kk = 0; kk < 4; kk++) {
                    float p = pa[kk];
#pragma unroll
                    for (int c = 0; c < 4; c++) {
                        float4 vv = *(const float4*)(Vs + (k4 + kk) * APITCH + sub * 16 + c * 4);
                        acc[c * 4 + 0] += p * vv.x; acc[c * 4 + 1] += p * vv.y;
                        acc[c * 4 + 2] += p * vv.z; acc[c * 4 + 3] += p * vv.w;
                    }
                }
            }
        }
    }
    float inv = 1.f / l_i;
    float* op = Oc + (size_t)(b * CAP_ + q) * D_ + h * HD_ + sub * 16;
#pragma unroll
    for (int c = 0; c < 4; c++)
        *(float4*)(op + c * 4) = make_float4(acc[c * 4] * inv, acc[c * 4 + 1] * inv,
                                             acc[c * 4 + 2] * inv, acc[c * 4 + 3] * inv);
}

// ------------------- elementwise / small kernels -------------------
__global__ void embed_k(const int* __restrict__ ids, const float* __restrict__ E,
                        const float* __restrict__ Pw, float* __restrict__ X) {
    int m = blockIdx.x;
    int t = m % T_;
    int id = ids[m];
    for (int i = threadIdx.x; i < D_; i += 256)
        X[(size_t)m * D_ + i] = E[(size_t)id * D_ + i] + Pw[(size_t)t * D_ + i];
}

__global__ void rmsnorm_k(const float* __restrict__ X, const float* __restrict__ w,
                          float* __restrict__ Yb) {
    int m = blockIdx.x;
    const float* x = X + (size_t)m * D_;
    float s = 0.f;
    for (int i = threadIdx.x; i < D_; i += 256) { float v = x[i]; s += v * v; }
    __shared__ float red[256];
    red[threadIdx.x] = s; __syncthreads();
    for (int st = 128; st > 0; st >>= 1) {
        if (threadIdx.x < st) red[threadIdx.x] += red[threadIdx.x + st];
        __syncthreads();
    }
    float scale = rsqrtf(red[0] / (float)D_ + 1e-6f);
    for (int i = threadIdx.x; i < D_; i += 256)
        Yb[(size_t)m * D_ + i] = x[i] * scale * w[i];
}

__global__ void swiglu_k(float* __restrict__ U, const float* __restrict__ V, int n) {
    int i = blockIdx.x * blockDim.x + threadIdx.x;
    if (i < n) {
        float u = U[i];
        float s = u / (1.f + expf(-u));
        U[i] = s * V[i];
    }
}

__global__ void router_score_k(const float* __restrict__ X, const float* __restrict__ rw,
                               float* __restrict__ sc) {
    int m = blockIdx.x;
    float s = 0.f;
    for (int i = threadIdx.x; i < D_; i += 256) s += X[(size_t)m * D_ + i] * rw[i];
    __shared__ float red[256];
    red[threadIdx.x] = s; __syncthreads();
    for (int st = 128; st > 0; st >>= 1) {
        if (threadIdx.x < st) red[threadIdx.x] += red[threadIdx.x + st];
        __syncthreads();
    }
    if (threadIdx.x == 0) sc[m] = red[0];
}

__global__ void topk_cidx_k(const float* __restrict__ sc, int* __restrict__ cidx) {
    int b = blockIdx.x, t = threadIdx.x;  // 512 threads
    __shared__ float s[T_];
    __shared__ int flag[T_];
    s[t] = sc[b * T_ + t];
    __syncthreads();
    float mine = s[t];
    int rank = 0;
    for (int j = 0; j < T_; j++) {
        float v = s[j];
        if (v > mine || (v == mine && j < t)) rank++;
    }
    int selected = (rank < CAP_) ? 1 : 0;
    flag[t] = selected;
    __syncthreads();
    if (selected) {
        int pos = 0;
        for (int j = 0; j < t; j++) pos += flag[j];
        cidx[b * CAP_ + pos] = b * T_ + t;
    }
}

__global__ void gather_k(const float* __restrict__ X, const int* __restrict__ cidx,
                         float* __restrict__ Yc) {
    int i = blockIdx.x;
    int row = cidx[i];
    for (int d = threadIdx.x; d < D_; d += 256)
        Yc[(size_t)i * D_ + d] = X[(size_t)row * D_ + d];
}

__global__ void scatter_k(const float* __restrict__ Yc, const int* __restrict__ cidx,
                          float* __restrict__ X) {
    int i = blockIdx.x;
    int row = cidx[i];
    for (int d = threadIdx.x; d < D_; d += 256)
        X[(size_t)row * D_ + d] = Yc[(size_t)i * D_ + d];
}

__global__ void memtopk_k(const float* __restrict__ SIM, const float* __restrict__ MV,
                          float* __restrict__ RETP) {
    int m = blockIdx.x;
    int tid = threadIdx.x;  // 256
    __shared__ float s[NMEM_];
    __shared__ float wts[TOPK_];
    __shared__ int idxs[TOPK_];
    __shared__ float rv[256];
    __shared__ int ri[256];
    const float invs = 0.03608439182435161f;  // 1/sqrt(768)
    for (int i = tid; i < NMEM_; i += 256) s[i] = SIM[(size_t)m * NMEM_ + i] * invs;
    __syncthreads();
    for (int j = 0; j < TOPK_; j++) {
        float bv = -1e30f; int bi = 0x7fffffff;
        for (int i = tid; i < NMEM_; i += 256) {
            if (s[i] > bv) { bv = s[i]; bi = i; }
        }
        rv[tid] = bv; ri[tid] = bi; __syncthreads();
        for (int st = 128; st > 0; st >>= 1) {
            if (tid < st) {
                if (rv[tid + st] > rv[tid] ||
                    (rv[tid + st] == rv[tid] && ri[tid + st] < ri[tid])) {
                    rv[tid] = rv[tid + st]; ri[tid] = ri[tid + st];
                }
            }
            __syncthreads();
        }
        if (tid == 0) { wts[j] = rv[0]; idxs[j] = ri[0]; s[ri[0]] = -1e30f; }
        __syncthreads();
    }
    if (tid == 0) {
        float mx = wts[0];
        float sum = 0.f;
        for (int j = 0; j < TOPK_; j++) { wts[j] = expf(wts[j] - mx); sum += wts[j]; }
        float inv = 1.f / sum;
        for (int j = 0; j < TOPK_; j++) wts[j] *= inv;
    }
    __syncthreads();
    for (int i = tid; i < D_; i += 256) {
        float a = 0.f;
#pragma unroll
        for (int j = 0; j < TOPK_; j++) a += wts[j] * MV[(size_t)idxs[j] * D_ + i];
        RETP[(size_t)m * D_ + i] = a;
    }
}

__global__ void concat_k(const float* __restrict__ X, const float* __restrict__ RET,
                         float* __restrict__ GI) {
    int m = blockIdx.x;
    for (int i = threadIdx.x; i < D_; i += 256) {
        GI[(size_t)m * 2 * D_ + i] = X[(size_t)m * D_ + i];
        GI[(size_t)m * 2 * D_ + D_ + i] = RET[(size_t)m * D_ + i];
    }
}

__global__ void gelu_bias_k(float* __restrict__ H1, const float* __restrict__ b1, int n) {
    int i = blockIdx.x * blockDim.x + threadIdx.x;
    if (i < n) {
        int col = i % (D_ / 2);
        float v = H1[i] + b1[col];
        H1[i] = 0.5f * v * (1.f + erff(v * 0.70710678118654752f));
    }
}

__global__ void gate_k(const float* __restrict__ H1, const float* __restrict__ w2,
                       const float* __restrict__ b2, const float* __restrict__ RET,
                       float* __restrict__ X) {
    int m = blockIdx.x;
    float s = 0.f;
    for (int i = threadIdx.x; i < D_ / 2; i += 256)
        s += H1[(size_t)m * (D_ / 2) + i] * w2[i];
    __shared__ float red[256];
    red[threadIdx.x] = s; __syncthreads();
    for (int st = 128; st > 0; st >>= 1) {
        if (threadIdx.x < st) red[threadIdx.x] += red[threadIdx.x + st];
        __syncthreads();
    }
    __shared__ float gsh;
    if (threadIdx.x == 0) gsh = 1.f / (1.f + expf(-(red[0] + b2[0])));
    __syncthreads();
    float g = gsh;
    for (int i = threadIdx.x; i < D_; i += 256)
        X[(size_t)m * D_ + i] += g * RET[(size_t)m * D_ + i];
}

// ------------------- host orchestration -------------------
static void gemm(const float* A, const float* Bw, float* C, int M, int N, int K, bool acc) {
    dim3 grid((N + 127) / 128, M / 128);
    if (N % 128 == 0) {
        if (acc) mmah_gemm_nt<true, false, 3><<<grid, 256>>>(A, Bw, C, M, N, K);
        else     mmah_gemm_nt<false, false, 3><<<grid, 256>>>(A, Bw, C, M, N, K);
    } else {
        if (acc) mmah_gemm_nt<true, true, 3><<<grid, 256>>>(A, Bw, C, M, N, K);
        else     mmah_gemm_nt<false, true, 3><<<grid, 256>>>(A, Bw, C, M, N, K);
    }
}

static void gemm_lm(const float* A, const float* Bw, float* C, int M, int N, int K) {
    dim3 grid((N + 127) / 128, M / 128);
    mmah_gemm_nt<false, true, 2><<<grid, 256>>>(A, Bw, C, M, N, K);
}

struct Ptrs {
    float *X, *Y, *Hb, *QKV, *ATT, *U, *V2, *SIM, *RETP, *RET, *GI, *H1, *SC;
    int* CIDX;
};

static void tblock_full(const Ptrs& p, const float* qkv_w, const float* out_w,
                        const float* n1, const float* n2, const float* w1,
                        const float* w2, const float* w3, float* x) {
    rmsnorm_k<<<BT_, 256>>>(x, n1, p.Hb);
    gemm(p.Hb, qkv_w, p.QKV, BT_, QKVD_, D_, false);
    fattn_k<<<dim3(T_ / 64, B_ * H_), 256, FA_SMEM>>>(p.QKV, p.ATT);
    gemm(p.ATT, out_w, x, BT_, D_, D_, true);
    rmsnorm_k<<<BT_, 256>>>(x, n2, p.Hb);
    gemm(p.Hb, w1, p.U, BT_, DFF_, D_, false);
    gemm(p.Hb, w2, p.V2, BT_, DFF_, D_, false);
    swiglu_k<<<(BT_ * DFF_ + 255) / 256, 256>>>(p.U, p.V2, BT_ * DFF_);
    gemm(p.U, w3, x, BT_, D_, DFF_, true);
}

static void tblock_mod(const Ptrs& p, const float* qkv_w, const float* out_w,
                       const float* n1, const float* n2, const float* w1,
                       const float* w2, const float* w3, const float* rw) {
    float* KV = p.QKV;
    float* Qc = p.QKV + (size_t)BT_ * (2 * D_);
    float* Xc = p.Y;
    float* Hc = p.RETP;
    float* Oc = p.ATT;

    router_score_k<<<BT_, 256>>>(p.X, rw, p.SC);
    topk_cidx_k<<<B_, T_>>>(p.SC, p.CIDX);
    rmsnorm_k<<<BT_, 256>>>(p.X, n1, p.Hb);
    gemm(p.Hb, qkv_w + (size_t)D_ * D_, KV, BT_, 2 * D_, D_, false);
    gather_k<<<BC_, 256>>>(p.Hb, p.CIDX, Hc);
    gemm(Hc, qkv_w, Qc, BC_, D_, D_, false);
    fattn_mod_k<<<B_ * H_, 256, FAM_SMEM>>>(Qc, KV, p.CIDX, Oc);
    gather_k<<<BC_, 256>>>(p.X, p.CIDX, Xc);
    gemm(Oc, out_w, Xc, BC_, D_, D_, true);
    rmsnorm_k<<<BC_, 256>>>(Xc, n2, Hc);
    gemm(Hc, w1, p.U, BC_, DFF_, D_, false);
    gemm(Hc, w2, p.V2, BC_, DFF_, D_, false);
    swiglu_k<<<(BC_ * DFF_ + 255) / 256, 256>>>(p.U, p.V2, BC_ * DFF_);
    gemm(p.U, w3, Xc, BC_, D_, DFF_, true);
    scatter_k<<<BC_, 256>>>(Xc, p.CIDX, p.X);
}

extern "C" void kernel_launch(void* const* d_in, const int* in_sizes, int n_in,
                              void* d_out, int out_size) {
    const int*   ids       = (const int*)d_in[0];
    const float* embed_w   = (const float*)d_in[1];
    const float* pos_w     = (const float*)d_in[2];
    const float* qkv_w     = (const float*)d_in[3];
    const float* out_w     = (const float*)d_in[4];
    const float* norm1_w   = (const float*)d_in[5];
    const float* norm2_w   = (const float*)d_in[6];
    const float* ff_w1     = (const float*)d_in[7];
    const float* ff_w2     = (const float*)d_in[8];
    const float* ff_w3     = (const float*)d_in[9];
    const float* router_w  = (const float*)d_in[10];
    const float* lat_qkv_w = (const float*)d_in[11];
    const float* lat_out_w = (const float*)d_in[12];
    const float* lat_n1    = (const float*)d_in[13];
    const float* lat_n2    = (const float*)d_in[14];
    const float* lat_w1    = (const float*)d_in[15];
    const float* lat_w2    = (const float*)d_in[16];
    const float* lat_w3    = (const float*)d_in[17];
    const float* mem_keys  = (const float*)d_in[18];
    const float* mem_values= (const float*)d_in[19];
    const float* mem_qp    = (const float*)d_in[20];
    const float* mem_op    = (const float*)d_in[21];
    const float* gate_w1   = (const float*)d_in[22];
    const float* gate_b1   = (const float*)d_in[23];
    const float* gate_w2   = (const float*)d_in[24];
    const float* gate_b2   = (const float*)d_in[25];
    const float* final_nw  = (const float*)d_in[26];
    float* out = (float*)d_out;

    static bool attr_done = false;
    if (!attr_done) {
        cudaFuncSetAttribute(fattn_k, cudaFuncAttributeMaxDynamicSharedMemorySize, FA_SMEM);
        cudaFuncSetAttribute(fattn_mod_k, cudaFuncAttributeMaxDynamicSharedMemorySize, FAM_SMEM);
        cudaFuncSetAttribute(fattn_k, cudaFuncAttributePreferredSharedMemoryCarveout, 100);
        cudaFuncSetAttribute(fattn_mod_k, cudaFuncAttributePreferredSharedMemoryCarveout, 100);
        attr_done = true;
    }

    Ptrs p;
    cudaGetSymbolAddress((void**)&p.X, g_X);
    cudaGetSymbolAddress((void**)&p.Y, g_Y);
    cudaGetSymbolAddress((void**)&p.Hb, g_Hb);
    cudaGetSymbolAddress((void**)&p.QKV, g_QKV);
    cudaGetSymbolAddress((void**)&p.ATT, g_ATT);
    cudaGetSymbolAddress((void**)&p.U, g_U);
    cudaGetSymbolAddress((void**)&p.V2, g_V2);
    cudaGetSymbolAddress((void**)&p.SIM, g_SIM);
    cudaGetSymbolAddress((void**)&p.RETP, g_RETP);
    cudaGetSymbolAddress((void**)&p.RET, g_RET);
    cudaGetSymbolAddress((void**)&p.GI, g_GI);
    cudaGetSymbolAddress((void**)&p.H1, g_H1);
    cudaGetSymbolAddress((void**)&p.SC, g_SC);
    cudaGetSymbolAddress((void**)&p.CIDX, g_CIDX);

    embed_k<<<BT_, 256>>>(ids, embed_w, pos_w, p.X);

    for (int i = 0; i < L_; i++) {
        const float* qw = qkv_w + (size_t)i * QKVD_ * D_;
        const float* ow = out_w + (size_t)i * D_ * D_;
        const float* n1 = norm1_w + (size_t)i * D_;
        const float* n2 = norm2_w + (size_t)i * D_;
        const float* w1 = ff_w1 + (size_t)i * DFF_ * D_;
        const float* w2 = ff_w2 + (size_t)i * DFF_ * D_;
        const float* w3 = ff_w3 + (size_t)i * D_ * DFF_;
        if (i % 2 == 1)
            tblock_mod(p, qw, ow, n1, n2, w1, w2, w3, router_w + (size_t)i * D_);
        else
            tblock_full(p, qw, ow, n1, n2, w1, w2, w3, p.X);
    }

    for (int it = 0; it < NLAT_; it++)
        tblock_full(p, lat_qkv_w, lat_out_w, lat_n1, lat_n2, lat_w1, lat_w2, lat_w3, p.X);

    // kNN memory retrieval
    gemm(p.X, mem_qp, p.Hb, BT_, D_, D_, false);
    gemm(p.Hb, mem_keys, p.SIM, BT_, NMEM_, D_, false);
    memtopk_k<<<BT_, 256>>>(p.SIM, mem_values, p.RETP);
    gemm(p.RETP, mem_op, p.RET, BT_, D_, D_, false);
    concat_k<<<BT_, 256>>>(p.X, p.RET, p.GI);
    gemm(p.GI, gate_w1, p.H1, BT_, D_ / 2, 2 * D_, false);
    gelu_bias_k<<<(BT_ * (D_ / 2) + 255) / 256, 256>>>(p.H1, gate_b1, BT_ * (D_ / 2));
    gate_k<<<BT_, 256>>>(p.H1, gate_w2, gate_b2, p.RET, p.X);

    // final norm + tied LM head (2-term split: no downstream selections)
    rmsnorm_k<<<BT_, 256>>>(p.X, final_nw, p.Hb);
    gemm_lm(p.Hb, embed_w, out, BT_, VOCAB_, D_);
}